// round 1
// baseline (speedup 1.0000x reference)
#include <cuda_runtime.h>
#include <stdint.h>
#include <math.h>

// Problem shape (fixed by the dataset problem)
#define NN 100000      // nodes
#define NE 1024        // hyperedges
#define NC 128         // channels
#define EDGE_CAP 2048  // max nodes per edge (Binomial(1e5,0.01): mean 1000, sigma 31 -> +33 sigma headroom)
#define NODE_CAP 64    // max edges per node (Binomial(1024,0.01): mean 10.2, sigma 3.2 -> +17 sigma headroom)
#define FEPS 1e-8f

// ---- device scratch (static; no runtime allocation) ----
__device__ int      g_edge_cnt[NE];                       // per-edge member count
__device__ int      g_csr[(size_t)NE * EDGE_CAP];         // edge -> node ids
__device__ uint16_t g_csc[(size_t)NN * NODE_CAP];         // node -> edge ids
__device__ int      g_deg[NN];                            // node degree
__device__ float    g_heW2[(size_t)NE * NC];              // (he * attn) @ W2
__device__ float    g_t[NN];                              // norm(x_i) * deg_i
__device__ int      g_deg_max;
__device__ unsigned g_t_max_bits;

// ---- K0: zero per-launch state ----
__global__ void k0_zero() {
    const int i = threadIdx.x;          // launched with NE threads
    g_edge_cnt[i] = 0;
    if (i == 0) { g_deg_max = 0; g_t_max_bits = 0u; }
}

// ---- K1: one warp per incidence row; build CSR + CSC + degrees ----
__global__ void __launch_bounds__(1024) k1_build(const float4* __restrict__ inc4) {
    const int lane = threadIdx.x & 31;
    const int wip  = threadIdx.x >> 5;
    const int node = blockIdx.x * 32 + wip;   // grid = NN/32 blocks exactly
    __shared__ int s_cnt[32];
    __shared__ int s_deg[32];
    if (lane == 0) s_cnt[wip] = 0;
    __syncwarp();

    const float4* row = inc4 + (size_t)node * (NE / 4);
#pragma unroll
    for (int j = 0; j < NE / 128; ++j) {      // 8 iterations, coalesced 512B/warp
        const int   idx   = j * 32 + lane;
        const float4 v    = row[idx];
        const int   ebase = idx * 4;
        if (v.x != 0.0f) {
            const int e = ebase + 0;
            const int p = atomicAdd(&g_edge_cnt[e], 1);
            if (p < EDGE_CAP) g_csr[(size_t)e * EDGE_CAP + p] = node;
            const int k = atomicAdd(&s_cnt[wip], 1);
            if (k < NODE_CAP) g_csc[(size_t)node * NODE_CAP + k] = (uint16_t)e;
        }
        if (v.y != 0.0f) {
            const int e = ebase + 1;
            const int p = atomicAdd(&g_edge_cnt[e], 1);
            if (p < EDGE_CAP) g_csr[(size_t)e * EDGE_CAP + p] = node;
            const int k = atomicAdd(&s_cnt[wip], 1);
            if (k < NODE_CAP) g_csc[(size_t)node * NODE_CAP + k] = (uint16_t)e;
        }
        if (v.z != 0.0f) {
            const int e = ebase + 2;
            const int p = atomicAdd(&g_edge_cnt[e], 1);
            if (p < EDGE_CAP) g_csr[(size_t)e * EDGE_CAP + p] = node;
            const int k = atomicAdd(&s_cnt[wip], 1);
            if (k < NODE_CAP) g_csc[(size_t)node * NODE_CAP + k] = (uint16_t)e;
        }
        if (v.w != 0.0f) {
            const int e = ebase + 3;
            const int p = atomicAdd(&g_edge_cnt[e], 1);
            if (p < EDGE_CAP) g_csr[(size_t)e * EDGE_CAP + p] = node;
            const int k = atomicAdd(&s_cnt[wip], 1);
            if (k < NODE_CAP) g_csc[(size_t)node * NODE_CAP + k] = (uint16_t)e;
        }
    }
    __syncwarp();
    if (lane == 0) {
        const int d = s_cnt[wip];
        g_deg[node] = d;
        s_deg[wip]  = d;
    }
    __syncthreads();
    if (threadIdx.x < 32) {
        int d = s_deg[threadIdx.x];
#pragma unroll
        for (int o = 16; o; o >>= 1) d = max(d, __shfl_xor_sync(0xffffffffu, d, o));
        if (threadIdx.x == 0) atomicMax(&g_deg_max, d);
    }
}

// ---- K2: softmax over edge_attention + Shannon entropy (1 block, NE threads) ----
__global__ void __launch_bounds__(1024) k2_softmax(const float* __restrict__ ea,
                                                   float* __restrict__ attn_out,
                                                   float* __restrict__ ent_out) {
    __shared__ float sred[32];
    __shared__ float sbc;
    const int t    = threadIdx.x;
    const int lane = t & 31;
    const int wid  = t >> 5;
    const float x  = ea[t];

    // max
    float v = x;
#pragma unroll
    for (int o = 16; o; o >>= 1) v = fmaxf(v, __shfl_xor_sync(0xffffffffu, v, o));
    if (lane == 0) sred[wid] = v;
    __syncthreads();
    if (wid == 0) {
        v = sred[lane];
#pragma unroll
        for (int o = 16; o; o >>= 1) v = fmaxf(v, __shfl_xor_sync(0xffffffffu, v, o));
        if (lane == 0) sbc = v;
    }
    __syncthreads();
    const float m = sbc;
    __syncthreads();

    // sum exp
    const float ex = expf(x - m);
    v = ex;
#pragma unroll
    for (int o = 16; o; o >>= 1) v += __shfl_xor_sync(0xffffffffu, v, o);
    if (lane == 0) sred[wid] = v;
    __syncthreads();
    if (wid == 0) {
        v = sred[lane];
#pragma unroll
        for (int o = 16; o; o >>= 1) v += __shfl_xor_sync(0xffffffffu, v, o);
        if (lane == 0) sbc = v;
    }
    __syncthreads();
    const float s = sbc;
    __syncthreads();

    const float a = ex / s;
    attn_out[t] = a;

    // sum of attn (numerically ~1, computed faithfully)
    v = a;
#pragma unroll
    for (int o = 16; o; o >>= 1) v += __shfl_xor_sync(0xffffffffu, v, o);
    if (lane == 0) sred[wid] = v;
    __syncthreads();
    if (wid == 0) {
        v = sred[lane];
#pragma unroll
        for (int o = 16; o; o >>= 1) v += __shfl_xor_sync(0xffffffffu, v, o);
        if (lane == 0) sbc = v;
    }
    __syncthreads();
    const float s2 = sbc;
    __syncthreads();

    const float p = a / (s2 + FEPS);
    v = -p * logf(p + FEPS);
#pragma unroll
    for (int o = 16; o; o >>= 1) v += __shfl_xor_sync(0xffffffffu, v, o);
    if (lane == 0) sred[wid] = v;
    __syncthreads();
    if (wid == 0) {
        v = sred[lane];
#pragma unroll
        for (int o = 16; o; o >>= 1) v += __shfl_xor_sync(0xffffffffu, v, o);
        if (lane == 0) ent_out[0] = v;
    }
}

// ---- K3: per-edge gather-sum + fused (@W1+b1)*attn -> he, then @W2 -> heW2 ----
__global__ void __launch_bounds__(128) k3_edge(const float* __restrict__ nf,
                                               const float* __restrict__ W1,
                                               const float* __restrict__ b1,
                                               const float* __restrict__ W2,
                                               const float* __restrict__ attn,
                                               float* __restrict__ he_out) {
    const int e = blockIdx.x;
    const int c = threadIdx.x;   // 128 threads, one channel each
    __shared__ float sm[NC];
    __shared__ int   s_list[128];

    int cnt = g_edge_cnt[e];
    cnt = cnt < EDGE_CAP ? cnt : EDGE_CAP;
    const int* __restrict__ list = g_csr + (size_t)e * EDGE_CAP;

    float a0 = 0.f, a1 = 0.f, a2 = 0.f, a3 = 0.f, a4 = 0.f, a5 = 0.f, a6 = 0.f, a7 = 0.f;
    int k = 0;
    for (; k + 128 <= cnt; k += 128) {
        __syncthreads();
        s_list[c] = list[k + c];
        __syncthreads();
#pragma unroll 4
        for (int u = 0; u < 128; u += 8) {
            a0 += nf[(size_t)s_list[u + 0] * NC + c];
            a1 += nf[(size_t)s_list[u + 1] * NC + c];
            a2 += nf[(size_t)s_list[u + 2] * NC + c];
            a3 += nf[(size_t)s_list[u + 3] * NC + c];
            a4 += nf[(size_t)s_list[u + 4] * NC + c];
            a5 += nf[(size_t)s_list[u + 5] * NC + c];
            a6 += nf[(size_t)s_list[u + 6] * NC + c];
            a7 += nf[(size_t)s_list[u + 7] * NC + c];
        }
    }
    for (; k < cnt; ++k) a0 += nf[(size_t)list[k] * NC + c];
    const float hraw = ((a0 + a1) + (a2 + a3)) + ((a4 + a5) + (a6 + a7));

    __syncthreads();
    sm[c] = hraw;
    __syncthreads();
    float acc = b1[c];
#pragma unroll
    for (int kk = 0; kk < NC; ++kk) acc = fmaf(sm[kk], W1[kk * NC + c], acc);
    const float hes = acc * attn[e];
    he_out[(size_t)e * NC + c] = hes;

    __syncthreads();
    sm[c] = hes;
    __syncthreads();
    float acc2 = 0.f;
#pragma unroll
    for (int kk = 0; kk < NC; ++kk) acc2 = fmaf(sm[kk], W2[kk * NC + c], acc2);
    g_heW2[(size_t)e * NC + c] = acc2;
}

// ---- K4: one warp per node; gather heW2 rows + b2 + residual; fused norm for sensitivity ----
__global__ void __launch_bounds__(1024) k4_node(const float4* __restrict__ nf4,
                                                const float4* __restrict__ b24,
                                                float4* __restrict__ out4) {
    const int lane = threadIdx.x & 31;
    const int wip  = threadIdx.x >> 5;
    const int node = blockIdx.x * 32 + wip;   // grid = NN/32 exactly
    __shared__ float s_tmax[32];

    const int d  = g_deg[node];
    const int dl = d < NODE_CAP ? d : NODE_CAP;
    const uint16_t* __restrict__ el = g_csc + (size_t)node * NODE_CAP;
    const float4*   __restrict__ hw = (const float4*)g_heW2;

    float4 acc = make_float4(0.f, 0.f, 0.f, 0.f);
#pragma unroll 4
    for (int j = 0; j < dl; ++j) {
        const float4 h = hw[(int)el[j] * 32 + lane];
        acc.x += h.x; acc.y += h.y; acc.z += h.z; acc.w += h.w;
    }
    const float4 x  = nf4[(size_t)node * 32 + lane];
    const float4 bb = b24[lane];
    float4 o;
    o.x = acc.x + bb.x + x.x;
    o.y = acc.y + bb.y + x.y;
    o.z = acc.z + bb.z + x.z;
    o.w = acc.w + bb.w + x.w;
    out4[(size_t)node * 32 + lane] = o;

    float ss = x.x * x.x + x.y * x.y + x.z * x.z + x.w * x.w;
#pragma unroll
    for (int q = 16; q; q >>= 1) ss += __shfl_xor_sync(0xffffffffu, ss, q);
    const float tv = sqrtf(ss) * (float)d;
    if (lane == 0) { g_t[node] = tv; s_tmax[wip] = tv; }
    __syncthreads();
    if (threadIdx.x < 32) {
        float mm = s_tmax[threadIdx.x];
#pragma unroll
        for (int q = 16; q; q >>= 1) mm = fmaxf(mm, __shfl_xor_sync(0xffffffffu, mm, q));
        if (threadIdx.x == 0) atomicMax(&g_t_max_bits, __float_as_uint(mm));
    }
}

// ---- K5: finalize sensitivity ----
__global__ void k5_final(float* __restrict__ sens) {
    const int i = blockIdx.x * blockDim.x + threadIdx.x;
    if (i >= NN) return;
    const float inv1 = 1.0f / ((float)g_deg_max + FEPS);
    const float smax = __uint_as_float(g_t_max_bits) * inv1;
    sens[i] = (g_t[i] * inv1) / (smax + FEPS);
}

extern "C" void kernel_launch(void* const* d_in, const int* in_sizes, int n_in,
                              void* d_out, int out_size) {
    const float* nf  = (const float*)d_in[0];  // node_features (N, C)
    const float* inc = (const float*)d_in[1];  // incidence     (N, E)
    const float* W1  = (const float*)d_in[2];  // (C, C)
    const float* b1  = (const float*)d_in[3];  // (C,)
    const float* W2  = (const float*)d_in[4];  // (C, C)
    const float* b2  = (const float*)d_in[5];  // (C,)
    const float* ea  = (const float*)d_in[6];  // edge_attention (E,)

    float* out      = (float*)d_out;
    float* node_out = out;                                 // N*C
    float* he_out   = out + (size_t)NN * NC;               // E*C
    float* attn_out = he_out + (size_t)NE * NC;            // E
    float* sens_out = attn_out + NE;                       // N
    float* ent_out  = sens_out + NN;                       // 1

    k0_zero<<<1, NE>>>();
    k1_build<<<NN / 32, 1024>>>((const float4*)inc);
    k2_softmax<<<1, NE>>>(ea, attn_out, ent_out);
    k3_edge<<<NE, NC>>>(nf, W1, b1, W2, attn_out, he_out);
    k4_node<<<NN / 32, 1024>>>((const float4*)nf, (const float4*)b2, (float4*)node_out);
    k5_final<<<(NN + 1023) / 1024, 1024>>>(sens_out);
}

// round 2
// speedup vs baseline: 1.0335x; 1.0335x over previous
#include <cuda_runtime.h>
#include <stdint.h>
#include <math.h>

// Problem shape (fixed by the dataset problem)
#define NN 100000      // nodes
#define NE 1024        // hyperedges
#define NC 128         // channels
#define EDGE_CAP 2048  // max nodes per edge (Binomial(1e5,0.01): +33 sigma headroom)
#define NODE_CAP 64    // max edges per node (Binomial(1024,0.01): +17 sigma headroom)
#define FEPS 1e-8f

// ---- device scratch (static; no runtime allocation) ----
__device__ int      g_edge_cnt[NE];                       // per-edge member count
__device__ int      g_csr[(size_t)NE * EDGE_CAP];         // edge -> node ids
__device__ uint16_t g_csc[(size_t)NN * NODE_CAP];         // node -> edge ids
__device__ int      g_deg[NN];                            // node degree
__device__ float    g_heW2[(size_t)NE * NC];              // (he * attn) @ W2
__device__ float    g_t[NN];                              // norm(x_i) * deg_i
__device__ int      g_deg_max;
__device__ unsigned g_t_max_bits;

// ---- K0: zero per-launch state ----
__global__ void k0_zero() {
    const int i = threadIdx.x;          // launched with NE threads
    g_edge_cnt[i] = 0;
    if (i == 0) { g_deg_max = 0; g_t_max_bits = 0u; }
}

// ---- K1: one warp per incidence row; build CSR + CSC + degrees ----
__global__ void __launch_bounds__(1024) k1_build(const float4* __restrict__ inc4) {
    const int lane = threadIdx.x & 31;
    const int wip  = threadIdx.x >> 5;
    const int node = blockIdx.x * 32 + wip;   // grid = NN/32 blocks exactly
    __shared__ int s_cnt[32];
    __shared__ int s_deg[32];
    if (lane == 0) s_cnt[wip] = 0;
    __syncwarp();

    const float4* row = inc4 + (size_t)node * (NE / 4);
#pragma unroll
    for (int j = 0; j < NE / 128; ++j) {      // 8 iterations, coalesced 512B/warp
        const int   idx   = j * 32 + lane;
        const float4 v    = row[idx];
        const int   ebase = idx * 4;
        if (v.x != 0.0f) {
            const int e = ebase + 0;
            const int p = atomicAdd(&g_edge_cnt[e], 1);
            if (p < EDGE_CAP) g_csr[(size_t)e * EDGE_CAP + p] = node;
            const int k = atomicAdd(&s_cnt[wip], 1);
            if (k < NODE_CAP) g_csc[(size_t)node * NODE_CAP + k] = (uint16_t)e;
        }
        if (v.y != 0.0f) {
            const int e = ebase + 1;
            const int p = atomicAdd(&g_edge_cnt[e], 1);
            if (p < EDGE_CAP) g_csr[(size_t)e * EDGE_CAP + p] = node;
            const int k = atomicAdd(&s_cnt[wip], 1);
            if (k < NODE_CAP) g_csc[(size_t)node * NODE_CAP + k] = (uint16_t)e;
        }
        if (v.z != 0.0f) {
            const int e = ebase + 2;
            const int p = atomicAdd(&g_edge_cnt[e], 1);
            if (p < EDGE_CAP) g_csr[(size_t)e * EDGE_CAP + p] = node;
            const int k = atomicAdd(&s_cnt[wip], 1);
            if (k < NODE_CAP) g_csc[(size_t)node * NODE_CAP + k] = (uint16_t)e;
        }
        if (v.w != 0.0f) {
            const int e = ebase + 3;
            const int p = atomicAdd(&g_edge_cnt[e], 1);
            if (p < EDGE_CAP) g_csr[(size_t)e * EDGE_CAP + p] = node;
            const int k = atomicAdd(&s_cnt[wip], 1);
            if (k < NODE_CAP) g_csc[(size_t)node * NODE_CAP + k] = (uint16_t)e;
        }
    }
    __syncwarp();
    if (lane == 0) {
        const int d = s_cnt[wip];
        g_deg[node] = d;
        s_deg[wip]  = d;
    }
    __syncthreads();
    if (threadIdx.x < 32) {
        int d = s_deg[threadIdx.x];
#pragma unroll
        for (int o = 16; o; o >>= 1) d = max(d, __shfl_xor_sync(0xffffffffu, d, o));
        if (threadIdx.x == 0) atomicMax(&g_deg_max, d);
    }
}

// ---- K2: softmax over edge_attention + Shannon entropy (1 block, NE threads) ----
__global__ void __launch_bounds__(1024) k2_softmax(const float* __restrict__ ea,
                                                   float* __restrict__ attn_out,
                                                   float* __restrict__ ent_out) {
    __shared__ float sred[32];
    __shared__ float sbc;
    const int t    = threadIdx.x;
    const int lane = t & 31;
    const int wid  = t >> 5;
    const float x  = ea[t];

    float v = x;
#pragma unroll
    for (int o = 16; o; o >>= 1) v = fmaxf(v, __shfl_xor_sync(0xffffffffu, v, o));
    if (lane == 0) sred[wid] = v;
    __syncthreads();
    if (wid == 0) {
        v = sred[lane];
#pragma unroll
        for (int o = 16; o; o >>= 1) v = fmaxf(v, __shfl_xor_sync(0xffffffffu, v, o));
        if (lane == 0) sbc = v;
    }
    __syncthreads();
    const float m = sbc;
    __syncthreads();

    const float ex = expf(x - m);
    v = ex;
#pragma unroll
    for (int o = 16; o; o >>= 1) v += __shfl_xor_sync(0xffffffffu, v, o);
    if (lane == 0) sred[wid] = v;
    __syncthreads();
    if (wid == 0) {
        v = sred[lane];
#pragma unroll
        for (int o = 16; o; o >>= 1) v += __shfl_xor_sync(0xffffffffu, v, o);
        if (lane == 0) sbc = v;
    }
    __syncthreads();
    const float s = sbc;
    __syncthreads();

    const float a = ex / s;
    attn_out[t] = a;

    v = a;
#pragma unroll
    for (int o = 16; o; o >>= 1) v += __shfl_xor_sync(0xffffffffu, v, o);
    if (lane == 0) sred[wid] = v;
    __syncthreads();
    if (wid == 0) {
        v = sred[lane];
#pragma unroll
        for (int o = 16; o; o >>= 1) v += __shfl_xor_sync(0xffffffffu, v, o);
        if (lane == 0) sbc = v;
    }
    __syncthreads();
    const float s2 = sbc;
    __syncthreads();

    const float p = a / (s2 + FEPS);
    v = -p * logf(p + FEPS);
#pragma unroll
    for (int o = 16; o; o >>= 1) v += __shfl_xor_sync(0xffffffffu, v, o);
    if (lane == 0) sred[wid] = v;
    __syncthreads();
    if (wid == 0) {
        v = sred[lane];
#pragma unroll
        for (int o = 16; o; o >>= 1) v += __shfl_xor_sync(0xffffffffu, v, o);
        if (lane == 0) ent_out[0] = v;
    }
}

// ---- K3 v2: 256 threads/edge; warps gather full rows via float4; fused matmuls ----
__global__ void __launch_bounds__(256) k3_edge(const float* __restrict__ nf,
                                               const float* __restrict__ W1,
                                               const float* __restrict__ b1,
                                               const float* __restrict__ W2,
                                               const float* __restrict__ attn,
                                               float* __restrict__ he_out) {
    const int e    = blockIdx.x;
    const int t    = threadIdx.x;
    const int w    = t >> 5;          // warp 0..7
    const int lane = t & 31;

    __shared__ int   s_idx[256];
    __shared__ float s_part[8][NC];   // 4 KB: per-warp partial row sums
    __shared__ float sm[NC];

    int cnt = g_edge_cnt[e];
    cnt = cnt < EDGE_CAP ? cnt : EDGE_CAP;
    const int*    __restrict__ list = g_csr + (size_t)e * EDGE_CAP;
    const float4* __restrict__ nf4  = (const float4*)nf;

    // each warp accumulates a full 128-ch row partial sum (lane holds 4 channels)
    float4 acc = make_float4(0.f, 0.f, 0.f, 0.f);
    for (int base = 0; base < cnt; base += 256) {
        const int n = min(256, cnt - base);
        __syncthreads();
        if (t < n) s_idx[t] = list[base + t];
        __syncthreads();
        const int lo = w * 32;
        const int hi = min(lo + 32, n);
#pragma unroll 4
        for (int r = lo; r < hi; ++r) {
            const float4 v = nf4[(size_t)s_idx[r] * 32 + lane];
            acc.x += v.x; acc.y += v.y; acc.z += v.z; acc.w += v.w;
        }
    }
    ((float4*)s_part[w])[lane] = acc;
    __syncthreads();

    // cross-warp reduce into sm[c]
    if (t < NC) {
        float h = 0.f;
#pragma unroll
        for (int ww = 0; ww < 8; ++ww) h += s_part[ww][t];
        sm[t] = h;
    }
    __syncthreads();

    // (@W1 + b1) * attn  -> he
    if (t < NC) {
        float acc1 = b1[t];
#pragma unroll
        for (int kk = 0; kk < NC; ++kk) acc1 = fmaf(sm[kk], W1[kk * NC + t], acc1);
        const float hes = acc1 * attn[e];
        he_out[(size_t)e * NC + t] = hes;
        s_part[0][t] = hes;
    }
    __syncthreads();

    // @W2 -> heW2 scratch
    if (t < NC) {
        float acc2 = 0.f;
#pragma unroll
        for (int kk = 0; kk < NC; ++kk) acc2 = fmaf(s_part[0][kk], W2[kk * NC + t], acc2);
        g_heW2[(size_t)e * NC + t] = acc2;
    }
}

// ---- K4 v2: one warp per node; 2-way unrolled float4 gather of heW2 rows ----
__global__ void __launch_bounds__(1024) k4_node(const float4* __restrict__ nf4,
                                                const float4* __restrict__ b24,
                                                float4* __restrict__ out4) {
    const int lane = threadIdx.x & 31;
    const int wip  = threadIdx.x >> 5;
    const int node = blockIdx.x * 32 + wip;   // grid = NN/32 exactly
    __shared__ float s_tmax[32];

    const int d  = g_deg[node];
    const int dl = d < NODE_CAP ? d : NODE_CAP;
    const uint16_t* __restrict__ el = g_csc + (size_t)node * NODE_CAP;
    const float4*   __restrict__ hw = (const float4*)g_heW2;

    float4 a0 = make_float4(0.f, 0.f, 0.f, 0.f);
    float4 a1 = make_float4(0.f, 0.f, 0.f, 0.f);
    int j = 0;
    for (; j + 2 <= dl; j += 2) {
        const float4 h0 = hw[(int)el[j]     * 32 + lane];
        const float4 h1 = hw[(int)el[j + 1] * 32 + lane];
        a0.x += h0.x; a0.y += h0.y; a0.z += h0.z; a0.w += h0.w;
        a1.x += h1.x; a1.y += h1.y; a1.z += h1.z; a1.w += h1.w;
    }
    if (j < dl) {
        const float4 h0 = hw[(int)el[j] * 32 + lane];
        a0.x += h0.x; a0.y += h0.y; a0.z += h0.z; a0.w += h0.w;
    }

    const float4 x  = nf4[(size_t)node * 32 + lane];
    const float4 bb = b24[lane];
    float4 o;
    o.x = a0.x + a1.x + bb.x + x.x;
    o.y = a0.y + a1.y + bb.y + x.y;
    o.z = a0.z + a1.z + bb.z + x.z;
    o.w = a0.w + a1.w + bb.w + x.w;
    out4[(size_t)node * 32 + lane] = o;

    float ss = x.x * x.x + x.y * x.y + x.z * x.z + x.w * x.w;
#pragma unroll
    for (int q = 16; q; q >>= 1) ss += __shfl_xor_sync(0xffffffffu, ss, q);
    const float tv = sqrtf(ss) * (float)d;
    if (lane == 0) { g_t[node] = tv; s_tmax[wip] = tv; }
    __syncthreads();
    if (threadIdx.x < 32) {
        float mm = s_tmax[threadIdx.x];
#pragma unroll
        for (int q = 16; q; q >>= 1) mm = fmaxf(mm, __shfl_xor_sync(0xffffffffu, mm, q));
        if (threadIdx.x == 0) atomicMax(&g_t_max_bits, __float_as_uint(mm));
    }
}

// ---- K5: finalize sensitivity ----
__global__ void k5_final(float* __restrict__ sens) {
    const int i = blockIdx.x * blockDim.x + threadIdx.x;
    if (i >= NN) return;
    const float inv1 = 1.0f / ((float)g_deg_max + FEPS);
    const float smax = __uint_as_float(g_t_max_bits) * inv1;
    sens[i] = (g_t[i] * inv1) / (smax + FEPS);
}

extern "C" void kernel_launch(void* const* d_in, const int* in_sizes, int n_in,
                              void* d_out, int out_size) {
    const float* nf  = (const float*)d_in[0];  // node_features (N, C)
    const float* inc = (const float*)d_in[1];  // incidence     (N, E)
    const float* W1  = (const float*)d_in[2];  // (C, C)
    const float* b1  = (const float*)d_in[3];  // (C,)
    const float* W2  = (const float*)d_in[4];  // (C, C)
    const float* b2  = (const float*)d_in[5];  // (C,)
    const float* ea  = (const float*)d_in[6];  // edge_attention (E,)

    float* out      = (float*)d_out;
    float* node_out = out;                                 // N*C
    float* he_out   = out + (size_t)NN * NC;               // E*C
    float* attn_out = he_out + (size_t)NE * NC;            // E
    float* sens_out = attn_out + NE;                       // N
    float* ent_out  = sens_out + NN;                       // 1

    k0_zero<<<1, NE>>>();
    k1_build<<<NN / 32, 1024>>>((const float4*)inc);
    k2_softmax<<<1, NE>>>(ea, attn_out, ent_out);
    k3_edge<<<NE, 256>>>(nf, W1, b1, W2, attn_out, he_out);
    k4_node<<<NN / 32, 1024>>>((const float4*)nf, (const float4*)b2, (float4*)node_out);
    k5_final<<<(NN + 1023) / 1024, 1024>>>(sens_out);
}